// round 11
// baseline (speedup 1.0000x reference)
#include <cuda_runtime.h>
#include <math.h>

// KnnLoss via spatial grid, warp-per-query, register-resident top-8 selection.
// B=2, N=8192 pts uniform in [0,1]^3, KS=16, K=8, radius 0.1.
// Neighbors with dist > 0.1 are replaced by self => contribute 0, so a
// 10x10x10 grid (cell = radius) holds everything that matters.
// Keys: 18-bit fixed-point d2 (monotone quantization of [0, 0.0101]) << 13 | idx.
// (d2, lowest-idx) order == jax.lax.top_k stable rule up to a 3.9e-8 d2 granule.
// Selection: per-lane sorted-4 list + 8 rounds of __reduce_min_sync (REDUX.MIN).
// Build: 16 blocks (all wave-1 resident), global-atomic hist -> block-0 scan
// (consumes counts to zero) -> flag release -> scatter. Counters restored to 0
// before exit => graph-replay safe.

#define B_CONST 2
#define N_CONST 8192
#define KS_CONST 16
#define GRID 10
#define NCELLS 1000
#define TOTPTS 16384
#define R2LIM 0.0101f
#define D2SCALE 25900000.0f                        // 0.0101 * SCALE = 261590 < 2^18
#define RTHRESH_U 259000u                          // floor(0.01 * SCALE)
#define WPB 4                                      // warps (queries) per block
#define MAIN_TPB 128
#define MAIN_BLOCKS (TOTPTS / WPB)                // 4096
#define NBUILD 16                                  // 8 build blocks per batch
#define BUILD_TPB 128
#define BPP 8                                      // consecutive points per build thread

__device__ int    g_count [B_CONST * NCELLS];      // zeroed by scan each launch
__device__ int    g_cursor[B_CONST * NCELLS];
__device__ int    g_start [B_CONST * (NCELLS + 1)];
__device__ float4 g_sorted[TOTPTS];                // (x, y, z, idx-as-float-bits)
__device__ float  g_partials[MAIN_BLOCKS];
__device__ int    g_done;
__device__ int    g_A, g_B, g_C;                   // all restored to 0 in-kernel

__device__ __forceinline__ int ld_cg(const int* p) {
    int v;
    asm volatile("ld.global.cg.b32 %0, [%1];" : "=r"(v) : "l"(p));
    return v;
}

__device__ __forceinline__ int cell_of(float x, float y, float z) {
    int cx = min(max((int)(x * (float)GRID), 0), GRID - 1);
    int cy = min(max((int)(y * (float)GRID), 0), GRID - 1);
    int cz = min(max((int)(z * (float)GRID), 0), GRID - 1);
    return cx + GRID * (cy + GRID * cz);           // x fastest
}

// scan one batch's 1000 cell counts with 128 threads; consumes g_count -> 0
__device__ void scan_batch(int b, int tid, int* swsum) {
    const int lane = tid & 31, wd = tid >> 5;
    const int base = tid * 8;
    int loc[8];
    int sum = 0;
#pragma unroll
    for (int k = 0; k < 8; ++k) {
        int cell = base + k;
        int v = (cell < NCELLS) ? g_count[b * NCELLS + cell] : 0;
        loc[k] = v;
        sum += v;
    }
    int incl = sum;
#pragma unroll
    for (int o = 1; o < 32; o <<= 1) {
        int n = __shfl_up_sync(0xFFFFFFFFu, incl, o);
        if (lane >= o) incl += n;
    }
    if (lane == 31) swsum[wd] = incl;
    __syncthreads();
    int woff = 0;
    if (wd > 0) woff += swsum[0];
    if (wd > 1) woff += swsum[1];
    if (wd > 2) woff += swsum[2];
    int run = incl - sum + woff;                   // exclusive prefix
#pragma unroll
    for (int k = 0; k < 8; ++k) {
        int cell = base + k;
        if (cell < NCELLS) {
            g_start [b * (NCELLS + 1) + cell] = run;
            g_cursor[b * NCELLS + cell]       = run;
            run += loc[k];
            g_count [b * NCELLS + cell]       = 0;  // consume -> replay-clean
        }
    }
    if (tid == 0) g_start[b * (NCELLS + 1) + NCELLS] = N_CONST;
    __syncthreads();
}

__global__ __launch_bounds__(BUILD_TPB) void k_build(const float* __restrict__ pc) {
    __shared__ int sscan[4];

    const int bb    = blockIdx.x;
    const int b     = bb >> 3;
    const int chunk = bb & 7;
    const int tid   = threadIdx.x;
    const float* pcb = pc + (size_t)b * N_CONST * 3;

    // 8 consecutive points per thread = 6 float4 loads
    const float4* pv = reinterpret_cast<const float4*>(pcb)
                     + (size_t)chunk * 768 + (size_t)tid * 6;
    float4 v0 = __ldg(pv + 0), v1 = __ldg(pv + 1), v2 = __ldg(pv + 2);
    float4 v3 = __ldg(pv + 3), v4 = __ldg(pv + 4), v5 = __ldg(pv + 5);

    float px[BPP], py[BPP], pz[BPP];
    px[0] = v0.x; py[0] = v0.y; pz[0] = v0.z;
    px[1] = v0.w; py[1] = v1.x; pz[1] = v1.y;
    px[2] = v1.z; py[2] = v1.w; pz[2] = v2.x;
    px[3] = v2.y; py[3] = v2.z; pz[3] = v2.w;
    px[4] = v3.x; py[4] = v3.y; pz[4] = v3.z;
    px[5] = v3.w; py[5] = v4.x; pz[5] = v4.y;
    px[6] = v4.z; py[6] = v4.w; pz[6] = v5.x;
    px[7] = v5.y; py[7] = v5.z; pz[7] = v5.w;

    int pcell[BPP];
#pragma unroll
    for (int k = 0; k < BPP; ++k)
        pcell[k] = cell_of(px[k], py[k], pz[k]);
#pragma unroll
    for (int k = 0; k < BPP; ++k)
        atomicAdd(&g_count[b * NCELLS + pcell[k]], 1);
    __threadfence();
    __syncthreads();
    if (tid == 0) atomicAdd(&g_A, 1);

    if (bb == 0) {
        if (tid == 0) {
            while (ld_cg(&g_A) != NBUILD) __nanosleep(32);
            g_A = 0;                               // restore (no one reads it again)
        }
        __syncthreads();
        __threadfence();
        scan_batch(0, tid, sscan);
        scan_batch(1, tid, sscan);
        __threadfence();
        __syncthreads();
        if (tid == 0) atomicExch(&g_B, 1);
    } else {
        if (tid == 0) { while (ld_cg(&g_B) != 1) __nanosleep(64); }
        __syncthreads();
        __threadfence();
    }

    // scatter (points held in registers)
#pragma unroll
    for (int k = 0; k < BPP; ++k) {
        int i   = chunk * 1024 + tid * BPP + k;
        int pos = atomicAdd(&g_cursor[b * NCELLS + pcell[k]], 1);
        g_sorted[b * N_CONST + pos] = make_float4(px[k], py[k], pz[k], __int_as_float(i));
    }
    __threadfence();
    __syncthreads();
    if (tid == 0) atomicAdd(&g_C, 1);

    if (bb == 0 && tid == 0) {                     // restore B,C for next replay
        while (ld_cg(&g_C) != NBUILD) __nanosleep(64);
        g_B = 0;
        g_C = 0;
        g_done = 0;
    }
}

// ---------------- main: warp-per-query knn + loss + fused finalize ----------------

__global__ __launch_bounds__(MAIN_TPB) void knn_loss_main(const float* __restrict__ mask,
                                                          float* __restrict__ out) {
    __shared__ float swacc[WPB];
    __shared__ float sred[MAIN_TPB];
    __shared__ int slast;

    const int warp  = threadIdx.x >> 5;
    const int lane  = threadIdx.x & 31;
    const int qslot = blockIdx.x * WPB + warp;
    const int b     = qslot >> 13;
    const int s     = qslot & (N_CONST - 1);

    const float4 me = g_sorted[b * N_CONST + s];     // broadcast across warp
    const float qx = me.x, qy = me.y, qz = me.z;
    const int   qi = __float_as_int(me.w);

    const int cx = min(max((int)(qx * (float)GRID), 0), GRID - 1);
    const int cy = min(max((int)(qy * (float)GRID), 0), GRID - 1);
    const int cz = min(max((int)(qz * (float)GRID), 0), GRID - 1);
    const int x0 = max(cx - 1, 0), x1 = min(cx + 1, GRID - 1);
    const int w  = x1 - x0 + 1;

    const int*    startb  = g_start  + b * (NCELLS + 1);
    const float4* sortedb = g_sorted + b * N_CONST;

    // lanes 0..8: fetch row bounds in parallel (validity + slab prune folded in)
    int beg_l = 0, end_l = 0;
    if (lane < 9) {
        const int rz = lane / 3;
        const int ry = lane - rz * 3;
        const int iyy = cy + ry - 1, izz = cz + rz - 1;
        bool valid = ((unsigned)iyy < GRID) && ((unsigned)izz < GRID);
        float fy = (float)iyy * 0.1f, fz = (float)izz * 0.1f;
        float dyv = fmaxf(fmaxf(fy - qy, qy - (fy + 0.1f)), 0.0f);
        float dzv = fmaxf(fmaxf(fz - qz, qz - (fz + 0.1f)), 0.0f);
        if (valid && (dyv * dyv + dzv * dzv <= R2LIM)) {
            int c0 = x0 + GRID * (iyy + GRID * izz);
            beg_l = __ldg(startb + c0);
            end_l = __ldg(startb + c0 + w);
        }
    }

    // per-lane sorted-4 smallest keys
    unsigned s0 = 0xFFFFFFFFu, s1 = 0xFFFFFFFFu, s2 = 0xFFFFFFFFu, s3 = 0xFFFFFFFFu;

#pragma unroll
    for (int r = 0; r < 9; ++r) {
        const int beg = __shfl_sync(0xFFFFFFFFu, beg_l, r);
        const int end = __shfl_sync(0xFFFFFFFFu, end_l, r);
        for (int p0 = beg; p0 < end; p0 += 32) {                        // uniform
            const int p = p0 + lane;
            unsigned kk = 0xFFFFFFFFu;
            if (p < end) {
                float4 a = __ldg(sortedb + p);
                float dx = qx - a.x, dy = qy - a.y, dz = qz - a.z;
                float d2 = fmaf(dx, dx, fmaf(dy, dy, dz * dz));
                if (d2 <= R2LIM)
                    kk = ((unsigned)(d2 * D2SCALE) << 13)
                       | (unsigned)__float_as_int(a.w);
            }
            // branchless insert into sorted-4 (7 IMNMX)
            unsigned a0 = min(s0, kk), b0 = max(s0, kk);
            unsigned c1 = min(s1, b0), d1 = max(s1, b0);
            unsigned e2 = min(s2, d1), f2 = max(s2, d1);
            s3 = min(s3, f2);
            s0 = a0; s1 = c1; s2 = e2;
        }
    }

    // prefetch own mask row — overlaps the REDUX chain below
    const float* maskb = mask + (size_t)b * N_CONST * KS_CONST;
    const float4* mrow = reinterpret_cast<const float4*>(maskb + (size_t)qi * KS_CONST);
    float4 m0, m1, m2, m3;
    if (lane < 8) {
        m0 = __ldg(mrow);     m1 = __ldg(mrow + 1);
        m2 = __ldg(mrow + 2); m3 = __ldg(mrow + 3);
    }

    // ---- extract global top-8 via REDUX.MIN; winner r lands on lane r ----
    unsigned mykey = 0xFFFFFFFFu;
#pragma unroll
    for (int r = 0; r < 8; ++r) {
        unsigned wv = __reduce_min_sync(0xFFFFFFFFu, s0);
        if (lane == r) mykey = wv;
        bool own = (s0 == wv) && (wv != 0xFFFFFFFFu);
        s0 = own ? s1 : s0;
        s1 = own ? s2 : s1;
        s2 = own ? s3 : s2;
        s3 = own ? 0xFFFFFFFFu : s3;
    }

    // ---- loss terms: lanes 0-7 gather their neighbor's mask row ----
    float term = 0.0f;
    if (lane < 8 && mykey != 0xFFFFFFFFu) {
        unsigned uq = mykey >> 13;
        int      nb = (int)(mykey & 8191u);
        if (uq <= RTHRESH_U && nb != qi) {       // in radius, not self
            const float4* nrow = reinterpret_cast<const float4*>(maskb + (size_t)nb * KS_CONST);
            float4 n0 = __ldg(nrow), n1 = __ldg(nrow + 1), n2 = __ldg(nrow + 2), n3 = __ldg(nrow + 3);
            term  = fabsf(m0.x - n0.x) + fabsf(m0.y - n0.y) + fabsf(m0.z - n0.z) + fabsf(m0.w - n0.w);
            term += fabsf(m1.x - n1.x) + fabsf(m1.y - n1.y) + fabsf(m1.z - n1.z) + fabsf(m1.w - n1.w);
            term += fabsf(m2.x - n2.x) + fabsf(m2.y - n2.y) + fabsf(m2.z - n2.z) + fabsf(m2.w - n2.w);
            term += fabsf(m3.x - n3.x) + fabsf(m3.y - n3.y) + fabsf(m3.z - n3.z) + fabsf(m3.w - n3.w);
        }
    }
    // fixed shfl tree (deterministic association, lanes >= 8 contribute 0)
    term += __shfl_down_sync(0xFFFFFFFFu, term, 16);
    term += __shfl_down_sync(0xFFFFFFFFu, term, 8);
    term += __shfl_down_sync(0xFFFFFFFFu, term, 4);
    term += __shfl_down_sync(0xFFFFFFFFu, term, 2);
    term += __shfl_down_sync(0xFFFFFFFFu, term, 1);
    if (lane == 0) swacc[warp] = term;

    // ---- deterministic block + grid reduction ----
    __syncthreads();
    if (threadIdx.x == 0) {
        float acc = (swacc[0] + swacc[1]) + (swacc[2] + swacc[3]);
        g_partials[blockIdx.x] = acc;
        __threadfence();
        int old = atomicAdd(&g_done, 1);
        slast = (old == MAIN_BLOCKS - 1) ? 1 : 0;
    }
    __syncthreads();
    if (slast) {
        int tid = threadIdx.x;
        float v = 0.0f;
#pragma unroll
        for (int j = 0; j < MAIN_BLOCKS / MAIN_TPB; ++j)
            v += __ldcg(&g_partials[tid + j * MAIN_TPB]);
        sred[tid] = v;
        __syncthreads();
#pragma unroll
        for (int r = MAIN_TPB / 2; r > 0; r >>= 1) {
            if (tid < r) sred[tid] += sred[tid + r];
            __syncthreads();
        }
        if (tid == 0) {
            out[0] = sred[0] / (float)(TOTPTS * 8);
            g_done = 0;                            // restore for next replay
        }
    }
}

extern "C" void kernel_launch(void* const* d_in, const int* in_sizes, int n_in,
                              void* d_out, int out_size) {
    const float* pc   = (const float*)d_in[0];   // (2, 8192, 3)  f32
    const float* mask = (const float*)d_in[1];   // (2, 8192, 16) f32
    float* out = (float*)d_out;                  // scalar f32

    k_build<<<NBUILD, BUILD_TPB>>>(pc);
    knn_loss_main<<<MAIN_BLOCKS, MAIN_TPB>>>(mask, out);
}

// round 12
// speedup vs baseline: 1.1360x; 1.1360x over previous
#include <cuda_runtime.h>
#include <math.h>

// KnnLoss via spatial grid, warp-per-query, register-resident top-8 selection.
// B=2, N=8192 pts uniform in [0,1]^3, KS=16, K=8, radius 0.1.
// Neighbors with dist > 0.1 are replaced by self => contribute 0, so a
// 10x10x10 grid (cell = radius) holds everything that matters.
// Keys: 18-bit fixed-point d2 (monotone quantization of [0, 0.0101]) << 13 | idx.
// (d2, lowest-idx) order == jax.lax.top_k stable rule up to a 3.9e-8 d2 granule.
// Scan: dual sub-streams per row (MLP=2, two independent sorted-4 IMNMX chains).
// Extraction: 8 rounds of __reduce_min_sync over min(headA, headB).
// Deterministic: extraction order is the unique sorted order; sums use fixed trees.

#define B_CONST 2
#define N_CONST 8192
#define KS_CONST 16
#define GRID 10
#define NCELLS 1000
#define TOTPTS 16384
#define R2LIM 0.0101f
#define D2SCALE 25900000.0f                        // 0.0101 * SCALE = 261590 < 2^18
#define RTHRESH_U 259000u                          // floor(0.01 * SCALE)
#define WPB 4                                      // warps (queries) per block
#define MAIN_TPB 128
#define MAIN_BLOCKS (TOTPTS / WPB)                // 4096
#define BUILD_TPB 1024
#define PPT 8                                      // consecutive points per build thread

__device__ int    g_start [B_CONST * (NCELLS + 1)];
__device__ float4 g_sorted[TOTPTS];               // (x, y, z, idx-as-float-bits)
__device__ float  g_partials[MAIN_BLOCKS];
__device__ int    g_done;

__device__ __forceinline__ int cell_of(float x, float y, float z) {
    int cx = min(max((int)(x * (float)GRID), 0), GRID - 1);
    int cy = min(max((int)(y * (float)GRID), 0), GRID - 1);
    int cz = min(max((int)(z * (float)GRID), 0), GRID - 1);
    return cx + GRID * (cy + GRID * cz);          // x fastest
}

// ---------------- fused grid build: one block per batch (R10 version) ----------------

__global__ __launch_bounds__(BUILD_TPB) void k_build(const float* __restrict__ pc) {
    __shared__ int scnt[BUILD_TPB];
    __shared__ int swoff[32];
    __shared__ int scur[NCELLS];

    const int b    = blockIdx.x;
    const int tid  = threadIdx.x;
    const int lane = tid & 31;
    const int wid  = tid >> 5;
    const float* pcb = pc + (size_t)b * N_CONST * 3;

    scnt[tid] = 0;
    __syncthreads();

    // one pass: 8 consecutive points = 6 float4 loads; keep all in registers
    const float4* pv = reinterpret_cast<const float4*>(pcb) + (size_t)tid * (3 * PPT / 4);
    float4 v0 = __ldg(pv + 0), v1 = __ldg(pv + 1), v2 = __ldg(pv + 2);
    float4 v3 = __ldg(pv + 3), v4 = __ldg(pv + 4), v5 = __ldg(pv + 5);

    float px[PPT], py[PPT], pz[PPT];
    px[0] = v0.x; py[0] = v0.y; pz[0] = v0.z;
    px[1] = v0.w; py[1] = v1.x; pz[1] = v1.y;
    px[2] = v1.z; py[2] = v1.w; pz[2] = v2.x;
    px[3] = v2.y; py[3] = v2.z; pz[3] = v2.w;
    px[4] = v3.x; py[4] = v3.y; pz[4] = v3.z;
    px[5] = v3.w; py[5] = v4.x; pz[5] = v4.y;
    px[6] = v4.z; py[6] = v4.w; pz[6] = v5.x;
    px[7] = v5.y; py[7] = v5.z; pz[7] = v5.w;

    int pcell[PPT];
#pragma unroll
    for (int k = 0; k < PPT; ++k)
        pcell[k] = cell_of(px[k], py[k], pz[k]);
#pragma unroll
    for (int k = 0; k < PPT; ++k)
        atomicAdd(&scnt[pcell[k]], 1);
    __syncthreads();

    int c = scnt[tid];
    int v = c;
#pragma unroll
    for (int o = 1; o < 32; o <<= 1) {
        int n = __shfl_up_sync(0xFFFFFFFFu, v, o);
        if (lane >= o) v += n;
    }
    if (lane == 31) swoff[wid] = v;
    __syncthreads();
    if (wid == 0) {
        int w = swoff[lane];
#pragma unroll
        for (int o = 1; o < 32; o <<= 1) {
            int n = __shfl_up_sync(0xFFFFFFFFu, w, o);
            if (lane >= o) w += n;
        }
        swoff[lane] = w;
    }
    __syncthreads();
    int incl = v + (wid ? swoff[wid - 1] : 0);
    int excl = incl - c;
    if (tid < NCELLS) {
        g_start[b * (NCELLS + 1) + tid] = excl;
        scur[tid] = excl;
    }
    if (tid == NCELLS - 1) g_start[b * (NCELLS + 1) + NCELLS] = incl;
    if (b == 0 && tid == 0) g_done = 0;
    __syncthreads();

#pragma unroll
    for (int k = 0; k < PPT; ++k) {
        int i = tid * PPT + k;
        int pos = atomicAdd(&scur[pcell[k]], 1);
        g_sorted[b * N_CONST + pos] = make_float4(px[k], py[k], pz[k], __int_as_float(i));
    }
}

// ---------------- main: warp-per-query knn + loss + fused finalize ----------------

__global__ __launch_bounds__(MAIN_TPB) void knn_loss_main(const float* __restrict__ mask,
                                                          float* __restrict__ out) {
    __shared__ float swacc[WPB];
    __shared__ float sred[MAIN_TPB];
    __shared__ int slast;

    const int warp  = threadIdx.x >> 5;
    const int lane  = threadIdx.x & 31;
    const int qslot = blockIdx.x * WPB + warp;
    const int b     = qslot >> 13;
    const int s     = qslot & (N_CONST - 1);

    const float4 me = g_sorted[b * N_CONST + s];     // broadcast across warp
    const float qx = me.x, qy = me.y, qz = me.z;
    const int   qi = __float_as_int(me.w);

    const int cx = min(max((int)(qx * (float)GRID), 0), GRID - 1);
    const int cy = min(max((int)(qy * (float)GRID), 0), GRID - 1);
    const int cz = min(max((int)(qz * (float)GRID), 0), GRID - 1);
    const int x0 = max(cx - 1, 0), x1 = min(cx + 1, GRID - 1);
    const int w  = x1 - x0 + 1;

    const int*    startb  = g_start  + b * (NCELLS + 1);
    const float4* sortedb = g_sorted + b * N_CONST;

    // lanes 0..8: fetch row bounds in parallel (validity + slab prune folded in)
    int beg_l = 0, end_l = 0;
    if (lane < 9) {
        const int rz = lane / 3;
        const int ry = lane - rz * 3;
        const int iyy = cy + ry - 1, izz = cz + rz - 1;
        bool valid = ((unsigned)iyy < GRID) && ((unsigned)izz < GRID);
        float fy = (float)iyy * 0.1f, fz = (float)izz * 0.1f;
        float dyv = fmaxf(fmaxf(fy - qy, qy - (fy + 0.1f)), 0.0f);
        float dzv = fmaxf(fmaxf(fz - qz, qz - (fz + 0.1f)), 0.0f);
        if (valid && (dyv * dyv + dzv * dzv <= R2LIM)) {
            int c0 = x0 + GRID * (iyy + GRID * izz);
            beg_l = __ldg(startb + c0);
            end_l = __ldg(startb + c0 + w);
        }
    }

    // dual per-lane sorted-4 lists (independent IMNMX chains)
    unsigned a0 = 0xFFFFFFFFu, a1 = 0xFFFFFFFFu, a2 = 0xFFFFFFFFu, a3 = 0xFFFFFFFFu;
    unsigned b0r = 0xFFFFFFFFu, b1r = 0xFFFFFFFFu, b2r = 0xFFFFFFFFu, b3r = 0xFFFFFFFFu;

#pragma unroll
    for (int r = 0; r < 9; ++r) {
        const int beg = __shfl_sync(0xFFFFFFFFu, beg_l, r);
        const int end = __shfl_sync(0xFFFFFFFFu, end_l, r);
        for (int p0 = beg; p0 < end; p0 += 64) {                        // uniform
            const int p = p0 + lane;
            const int q = p0 + 32 + lane;
            unsigned kA = 0xFFFFFFFFu, kB = 0xFFFFFFFFu;
            if (p < end) {
                float4 a = __ldg(sortedb + p);
                float dx = qx - a.x, dy = qy - a.y, dz = qz - a.z;
                float d2 = fmaf(dx, dx, fmaf(dy, dy, dz * dz));
                if (d2 <= R2LIM)
                    kA = ((unsigned)(d2 * D2SCALE) << 13)
                       | (unsigned)__float_as_int(a.w);
            }
            if (q < end) {
                float4 a = __ldg(sortedb + q);
                float dx = qx - a.x, dy = qy - a.y, dz = qz - a.z;
                float d2 = fmaf(dx, dx, fmaf(dy, dy, dz * dz));
                if (d2 <= R2LIM)
                    kB = ((unsigned)(d2 * D2SCALE) << 13)
                       | (unsigned)__float_as_int(a.w);
            }
            // two independent branchless sorted-4 inserts (7 IMNMX each)
            {
                unsigned t0 = min(a0, kA), u0 = max(a0, kA);
                unsigned t1 = min(a1, u0), u1 = max(a1, u0);
                unsigned t2 = min(a2, u1), u2 = max(a2, u1);
                a3 = min(a3, u2);
                a0 = t0; a1 = t1; a2 = t2;
            }
            {
                unsigned t0 = min(b0r, kB), u0 = max(b0r, kB);
                unsigned t1 = min(b1r, u0), u1 = max(b1r, u0);
                unsigned t2 = min(b2r, u1), u2 = max(b2r, u1);
                b3r = min(b3r, u2);
                b0r = t0; b1r = t1; b2r = t2;
            }
        }
    }

    // prefetch own mask row — overlaps the REDUX chain below
    const float* maskb = mask + (size_t)b * N_CONST * KS_CONST;
    const float4* mrow = reinterpret_cast<const float4*>(maskb + (size_t)qi * KS_CONST);
    float4 m0, m1, m2, m3;
    if (lane < 8) {
        m0 = __ldg(mrow);     m1 = __ldg(mrow + 1);
        m2 = __ldg(mrow + 2); m3 = __ldg(mrow + 3);
    }

    // ---- extract global top-8 via REDUX.MIN; winner r lands on lane r ----
    // keys are globally unique (idx in low bits) => at most one list owns wv
    unsigned mykey = 0xFFFFFFFFu;
#pragma unroll
    for (int r = 0; r < 8; ++r) {
        unsigned cur = min(a0, b0r);
        unsigned wv = __reduce_min_sync(0xFFFFFFFFu, cur);
        if (lane == r) mykey = wv;
        bool ownA = (a0 == wv) && (wv != 0xFFFFFFFFu);
        a0 = ownA ? a1 : a0;
        a1 = ownA ? a2 : a1;
        a2 = ownA ? a3 : a2;
        a3 = ownA ? 0xFFFFFFFFu : a3;
        bool ownB = (b0r == wv) && (wv != 0xFFFFFFFFu);
        b0r = ownB ? b1r : b0r;
        b1r = ownB ? b2r : b1r;
        b2r = ownB ? b3r : b2r;
        b3r = ownB ? 0xFFFFFFFFu : b3r;
    }

    // ---- loss terms: lanes 0-7 gather their neighbor's mask row ----
    float term = 0.0f;
    if (lane < 8 && mykey != 0xFFFFFFFFu) {
        unsigned uq = mykey >> 13;
        int      nb = (int)(mykey & 8191u);
        if (uq <= RTHRESH_U && nb != qi) {       // in radius, not self
            const float4* nrow = reinterpret_cast<const float4*>(maskb + (size_t)nb * KS_CONST);
            float4 n0 = __ldg(nrow), n1 = __ldg(nrow + 1), n2 = __ldg(nrow + 2), n3 = __ldg(nrow + 3);
            term  = fabsf(m0.x - n0.x) + fabsf(m0.y - n0.y) + fabsf(m0.z - n0.z) + fabsf(m0.w - n0.w);
            term += fabsf(m1.x - n1.x) + fabsf(m1.y - n1.y) + fabsf(m1.z - n1.z) + fabsf(m1.w - n1.w);
            term += fabsf(m2.x - n2.x) + fabsf(m2.y - n2.y) + fabsf(m2.z - n2.z) + fabsf(m2.w - n2.w);
            term += fabsf(m3.x - n3.x) + fabsf(m3.y - n3.y) + fabsf(m3.z - n3.z) + fabsf(m3.w - n3.w);
        }
    }
    // fixed shfl tree (deterministic association, lanes >= 8 contribute 0)
    term += __shfl_down_sync(0xFFFFFFFFu, term, 16);
    term += __shfl_down_sync(0xFFFFFFFFu, term, 8);
    term += __shfl_down_sync(0xFFFFFFFFu, term, 4);
    term += __shfl_down_sync(0xFFFFFFFFu, term, 2);
    term += __shfl_down_sync(0xFFFFFFFFu, term, 1);
    if (lane == 0) swacc[warp] = term;

    // ---- deterministic block + grid reduction ----
    __syncthreads();
    if (threadIdx.x == 0) {
        float acc = (swacc[0] + swacc[1]) + (swacc[2] + swacc[3]);
        g_partials[blockIdx.x] = acc;
        __threadfence();
        int old = atomicAdd(&g_done, 1);
        slast = (old == MAIN_BLOCKS - 1) ? 1 : 0;
    }
    __syncthreads();
    if (slast) {
        int tid = threadIdx.x;
        float v = 0.0f;
#pragma unroll
        for (int j = 0; j < MAIN_BLOCKS / MAIN_TPB; ++j)
            v += __ldcg(&g_partials[tid + j * MAIN_TPB]);
        sred[tid] = v;
        __syncthreads();
#pragma unroll
        for (int r = MAIN_TPB / 2; r > 0; r >>= 1) {
            if (tid < r) sred[tid] += sred[tid + r];
            __syncthreads();
        }
        if (tid == 0)
            out[0] = sred[0] / (float)(TOTPTS * 8);
    }
}

extern "C" void kernel_launch(void* const* d_in, const int* in_sizes, int n_in,
                              void* d_out, int out_size) {
    const float* pc   = (const float*)d_in[0];   // (2, 8192, 3)  f32
    const float* mask = (const float*)d_in[1];   // (2, 8192, 16) f32
    float* out = (float*)d_out;                  // scalar f32

    k_build<<<B_CONST, BUILD_TPB>>>(pc);
    knn_loss_main<<<MAIN_BLOCKS, MAIN_TPB>>>(mask, out);
}

// round 13
// speedup vs baseline: 1.2231x; 1.0767x over previous
#include <cuda_runtime.h>
#include <math.h>

// KnnLoss via spatial grid, warp-per-query, register-resident top-8 selection.
// B=2, N=8192 pts uniform in [0,1]^3, KS=16, K=8, radius 0.1.
// Neighbors with dist > 0.1 are replaced by self => contribute 0, so a
// 10x10x10 grid (cell = radius) holds everything that matters.
// Keys: 18-bit fixed-point d2 (monotone quantization of [0, 0.0101]) << 13 | idx.
// (d2, lowest-idx) order == jax.lax.top_k stable rule up to a 3.9e-8 d2 granule.
// Scan: row-granular software pipeline — row r+1's first chunk LDG issues
// before row r's insert chain (MLP=2 across rows, no dead-lane overhead).
// Selection: per-lane sorted-4 + 8 rounds of __reduce_min_sync (REDUX.MIN).
// Deterministic: extraction order is the unique sorted order; sums use fixed trees.

#define B_CONST 2
#define N_CONST 8192
#define KS_CONST 16
#define GRID 10
#define NCELLS 1000
#define TOTPTS 16384
#define R2LIM 0.0101f
#define D2SCALE 25900000.0f                        // 0.0101 * SCALE = 261590 < 2^18
#define RTHRESH_U 259000u                          // floor(0.01 * SCALE)
#define WPB 4                                      // warps (queries) per block
#define MAIN_TPB 128
#define MAIN_BLOCKS (TOTPTS / WPB)                // 4096
#define BUILD_TPB 1024
#define PPT 8                                      // consecutive points per build thread

__device__ int    g_start [B_CONST * (NCELLS + 1)];
__device__ float4 g_sorted[TOTPTS];               // (x, y, z, idx-as-float-bits)
__device__ float  g_partials[MAIN_BLOCKS];
__device__ int    g_done;

__device__ __forceinline__ int cell_of(float x, float y, float z) {
    int cx = min(max((int)(x * (float)GRID), 0), GRID - 1);
    int cy = min(max((int)(y * (float)GRID), 0), GRID - 1);
    int cz = min(max((int)(z * (float)GRID), 0), GRID - 1);
    return cx + GRID * (cy + GRID * cz);          // x fastest
}

// ---------------- fused grid build: one block per batch (R10 version) ----------------

__global__ __launch_bounds__(BUILD_TPB) void k_build(const float* __restrict__ pc) {
    __shared__ int scnt[BUILD_TPB];
    __shared__ int swoff[32];
    __shared__ int scur[NCELLS];

    const int b    = blockIdx.x;
    const int tid  = threadIdx.x;
    const int lane = tid & 31;
    const int wid  = tid >> 5;
    const float* pcb = pc + (size_t)b * N_CONST * 3;

    scnt[tid] = 0;
    __syncthreads();

    // one pass: 8 consecutive points = 6 float4 loads; keep all in registers
    const float4* pv = reinterpret_cast<const float4*>(pcb) + (size_t)tid * (3 * PPT / 4);
    float4 v0 = __ldg(pv + 0), v1 = __ldg(pv + 1), v2 = __ldg(pv + 2);
    float4 v3 = __ldg(pv + 3), v4 = __ldg(pv + 4), v5 = __ldg(pv + 5);

    float px[PPT], py[PPT], pz[PPT];
    px[0] = v0.x; py[0] = v0.y; pz[0] = v0.z;
    px[1] = v0.w; py[1] = v1.x; pz[1] = v1.y;
    px[2] = v1.z; py[2] = v1.w; pz[2] = v2.x;
    px[3] = v2.y; py[3] = v2.z; pz[3] = v2.w;
    px[4] = v3.x; py[4] = v3.y; pz[4] = v3.z;
    px[5] = v3.w; py[5] = v4.x; pz[5] = v4.y;
    px[6] = v4.z; py[6] = v4.w; pz[6] = v5.x;
    px[7] = v5.y; py[7] = v5.z; pz[7] = v5.w;

    int pcell[PPT];
#pragma unroll
    for (int k = 0; k < PPT; ++k)
        pcell[k] = cell_of(px[k], py[k], pz[k]);
#pragma unroll
    for (int k = 0; k < PPT; ++k)
        atomicAdd(&scnt[pcell[k]], 1);
    __syncthreads();

    int c = scnt[tid];
    int v = c;
#pragma unroll
    for (int o = 1; o < 32; o <<= 1) {
        int n = __shfl_up_sync(0xFFFFFFFFu, v, o);
        if (lane >= o) v += n;
    }
    if (lane == 31) swoff[wid] = v;
    __syncthreads();
    if (wid == 0) {
        int w = swoff[lane];
#pragma unroll
        for (int o = 1; o < 32; o <<= 1) {
            int n = __shfl_up_sync(0xFFFFFFFFu, w, o);
            if (lane >= o) w += n;
        }
        swoff[lane] = w;
    }
    __syncthreads();
    int incl = v + (wid ? swoff[wid - 1] : 0);
    int excl = incl - c;
    if (tid < NCELLS) {
        g_start[b * (NCELLS + 1) + tid] = excl;
        scur[tid] = excl;
    }
    if (tid == NCELLS - 1) g_start[b * (NCELLS + 1) + NCELLS] = incl;
    if (b == 0 && tid == 0) g_done = 0;
    __syncthreads();

#pragma unroll
    for (int k = 0; k < PPT; ++k) {
        int i = tid * PPT + k;
        int pos = atomicAdd(&scur[pcell[k]], 1);
        g_sorted[b * N_CONST + pos] = make_float4(px[k], py[k], pz[k], __int_as_float(i));
    }
}

// ---------------- main: warp-per-query knn + loss + fused finalize ----------------

__global__ __launch_bounds__(MAIN_TPB) void knn_loss_main(const float* __restrict__ mask,
                                                          float* __restrict__ out) {
    __shared__ float swacc[WPB];
    __shared__ float sred[MAIN_TPB];
    __shared__ int slast;

    const int warp  = threadIdx.x >> 5;
    const int lane  = threadIdx.x & 31;
    const int qslot = blockIdx.x * WPB + warp;
    const int b     = qslot >> 13;
    const int s     = qslot & (N_CONST - 1);

    const float4 me = g_sorted[b * N_CONST + s];     // broadcast across warp
    const float qx = me.x, qy = me.y, qz = me.z;
    const int   qi = __float_as_int(me.w);

    const int cx = min(max((int)(qx * (float)GRID), 0), GRID - 1);
    const int cy = min(max((int)(qy * (float)GRID), 0), GRID - 1);
    const int cz = min(max((int)(qz * (float)GRID), 0), GRID - 1);
    const int x0 = max(cx - 1, 0), x1 = min(cx + 1, GRID - 1);
    const int w  = x1 - x0 + 1;

    const int*    startb  = g_start  + b * (NCELLS + 1);
    const float4* sortedb = g_sorted + b * N_CONST;

    // lanes 0..8: fetch row bounds in parallel (validity + slab prune folded in)
    int beg_l = 0, end_l = 0;
    if (lane < 9) {
        const int rz = lane / 3;
        const int ry = lane - rz * 3;
        const int iyy = cy + ry - 1, izz = cz + rz - 1;
        bool valid = ((unsigned)iyy < GRID) && ((unsigned)izz < GRID);
        float fy = (float)iyy * 0.1f, fz = (float)izz * 0.1f;
        float dyv = fmaxf(fmaxf(fy - qy, qy - (fy + 0.1f)), 0.0f);
        float dzv = fmaxf(fmaxf(fz - qz, qz - (fz + 0.1f)), 0.0f);
        if (valid && (dyv * dyv + dzv * dzv <= R2LIM)) {
            int c0 = x0 + GRID * (iyy + GRID * izz);
            beg_l = __ldg(startb + c0);
            end_l = __ldg(startb + c0 + w);
        }
    }

    // per-lane sorted-4 smallest keys
    unsigned s0 = 0xFFFFFFFFu, s1 = 0xFFFFFFFFu, s2 = 0xFFFFFFFFu, s3 = 0xFFFFFFFFu;

    // row-granular software pipeline: row r+1's first-chunk LDG issues
    // before row r's compute/insert chain.
    int beg = __shfl_sync(0xFFFFFFFFu, beg_l, 0);
    int end = __shfl_sync(0xFFFFFFFFu, end_l, 0);
    float4 cur;
    bool curv = (beg + lane < end);
    if (curv) cur = __ldg(sortedb + beg + lane);

#pragma unroll
    for (int r = 0; r < 9; ++r) {
        int nbeg = 0, nend = 0;
        if (r < 8) {
            nbeg = __shfl_sync(0xFFFFFFFFu, beg_l, r + 1);
            nend = __shfl_sync(0xFFFFFFFFu, end_l, r + 1);
        }
        float4 nxt;
        bool nxtv = (r < 8) && (nbeg + lane < nend);
        if (nxtv) nxt = __ldg(sortedb + nbeg + lane);     // prefetch next row

        // process current row's first chunk
        {
            unsigned kk = 0xFFFFFFFFu;
            if (curv) {
                float dx = qx - cur.x, dy = qy - cur.y, dz = qz - cur.z;
                float d2 = fmaf(dx, dx, fmaf(dy, dy, dz * dz));
                if (d2 <= R2LIM)
                    kk = ((unsigned)(d2 * D2SCALE) << 13)
                       | (unsigned)__float_as_int(cur.w);
            }
            unsigned t0 = min(s0, kk), u0 = max(s0, kk);
            unsigned t1 = min(s1, u0), u1 = max(s1, u0);
            unsigned t2 = min(s2, u1), u2 = max(s2, u1);
            s3 = min(s3, u2);
            s0 = t0; s1 = t1; s2 = t2;
        }
        // rare overflow chunks (row > 32 candidates), uniform tail loop
        for (int p0 = beg + 32; p0 < end; p0 += 32) {
            const int p = p0 + lane;
            unsigned kk = 0xFFFFFFFFu;
            if (p < end) {
                float4 a = __ldg(sortedb + p);
                float dx = qx - a.x, dy = qy - a.y, dz = qz - a.z;
                float d2 = fmaf(dx, dx, fmaf(dy, dy, dz * dz));
                if (d2 <= R2LIM)
                    kk = ((unsigned)(d2 * D2SCALE) << 13)
                       | (unsigned)__float_as_int(a.w);
            }
            unsigned t0 = min(s0, kk), u0 = max(s0, kk);
            unsigned t1 = min(s1, u0), u1 = max(s1, u0);
            unsigned t2 = min(s2, u1), u2 = max(s2, u1);
            s3 = min(s3, u2);
            s0 = t0; s1 = t1; s2 = t2;
        }

        beg = nbeg; end = nend; cur = nxt; curv = nxtv;
    }

    // prefetch own mask row — overlaps the REDUX chain below
    const float* maskb = mask + (size_t)b * N_CONST * KS_CONST;
    const float4* mrow = reinterpret_cast<const float4*>(maskb + (size_t)qi * KS_CONST);
    float4 m0, m1, m2, m3;
    if (lane < 8) {
        m0 = __ldg(mrow);     m1 = __ldg(mrow + 1);
        m2 = __ldg(mrow + 2); m3 = __ldg(mrow + 3);
    }

    // ---- extract global top-8 via REDUX.MIN; winner r lands on lane r ----
    unsigned mykey = 0xFFFFFFFFu;
#pragma unroll
    for (int r = 0; r < 8; ++r) {
        unsigned wv = __reduce_min_sync(0xFFFFFFFFu, s0);
        if (lane == r) mykey = wv;
        bool own = (s0 == wv) && (wv != 0xFFFFFFFFu);
        s0 = own ? s1 : s0;
        s1 = own ? s2 : s1;
        s2 = own ? s3 : s2;
        s3 = own ? 0xFFFFFFFFu : s3;
    }

    // ---- loss terms: lanes 0-7 gather their neighbor's mask row ----
    float term = 0.0f;
    if (lane < 8 && mykey != 0xFFFFFFFFu) {
        unsigned uq = mykey >> 13;
        int      nb = (int)(mykey & 8191u);
        if (uq <= RTHRESH_U && nb != qi) {       // in radius, not self
            const float4* nrow = reinterpret_cast<const float4*>(maskb + (size_t)nb * KS_CONST);
            float4 n0 = __ldg(nrow), n1 = __ldg(nrow + 1), n2 = __ldg(nrow + 2), n3 = __ldg(nrow + 3);
            term  = fabsf(m0.x - n0.x) + fabsf(m0.y - n0.y) + fabsf(m0.z - n0.z) + fabsf(m0.w - n0.w);
            term += fabsf(m1.x - n1.x) + fabsf(m1.y - n1.y) + fabsf(m1.z - n1.z) + fabsf(m1.w - n1.w);
            term += fabsf(m2.x - n2.x) + fabsf(m2.y - n2.y) + fabsf(m2.z - n2.z) + fabsf(m2.w - n2.w);
            term += fabsf(m3.x - n3.x) + fabsf(m3.y - n3.y) + fabsf(m3.z - n3.z) + fabsf(m3.w - n3.w);
        }
    }
    // fixed shfl tree (deterministic association, lanes >= 8 contribute 0)
    term += __shfl_down_sync(0xFFFFFFFFu, term, 16);
    term += __shfl_down_sync(0xFFFFFFFFu, term, 8);
    term += __shfl_down_sync(0xFFFFFFFFu, term, 4);
    term += __shfl_down_sync(0xFFFFFFFFu, term, 2);
    term += __shfl_down_sync(0xFFFFFFFFu, term, 1);
    if (lane == 0) swacc[warp] = term;

    // ---- deterministic block + grid reduction ----
    __syncthreads();
    if (threadIdx.x == 0) {
        float acc = (swacc[0] + swacc[1]) + (swacc[2] + swacc[3]);
        g_partials[blockIdx.x] = acc;
        __threadfence();
        int old = atomicAdd(&g_done, 1);
        slast = (old == MAIN_BLOCKS - 1) ? 1 : 0;
    }
    __syncthreads();
    if (slast) {
        int tid = threadIdx.x;
        float v = 0.0f;
#pragma unroll
        for (int j = 0; j < MAIN_BLOCKS / MAIN_TPB; ++j)
            v += __ldcg(&g_partials[tid + j * MAIN_TPB]);
        sred[tid] = v;
        __syncthreads();
#pragma unroll
        for (int r = MAIN_TPB / 2; r > 0; r >>= 1) {
            if (tid < r) sred[tid] += sred[tid + r];
            __syncthreads();
        }
        if (tid == 0)
            out[0] = sred[0] / (float)(TOTPTS * 8);
    }
}

extern "C" void kernel_launch(void* const* d_in, const int* in_sizes, int n_in,
                              void* d_out, int out_size) {
    const float* pc   = (const float*)d_in[0];   // (2, 8192, 3)  f32
    const float* mask = (const float*)d_in[1];   // (2, 8192, 16) f32
    float* out = (float*)d_out;                  // scalar f32

    k_build<<<B_CONST, BUILD_TPB>>>(pc);
    knn_loss_main<<<MAIN_BLOCKS, MAIN_TPB>>>(mask, out);
}

// round 14
// speedup vs baseline: 1.2289x; 1.0047x over previous
#include <cuda_runtime.h>
#include <math.h>

// KnnLoss via spatial grid, warp-per-query, register-resident top-8 selection.
// B=2, N=8192 pts uniform in [0,1]^3, KS=16, K=8, radius 0.1.
// Neighbors with dist > 0.1 are replaced by self => contribute 0, so a
// 10x10x10 grid (cell = radius) holds everything that matters.
// Keys: 18-bit fixed-point d2 (monotone quantization of [0, 0.0101]) << 13 | idx.
// (d2, lowest-idx) order == jax.lax.top_k stable rule up to a 3.9e-8 d2 granule.
// Scan: row-granular software pipeline (row r+1's LDG before row r's inserts).
// Selection: per-lane sorted-4 + 8 rounds of __reduce_min_sync (REDUX.MIN).
// Build: ONE smem-atomic pass — histogram atomicAdd returns within-cell rank;
// scatter position = start[cell] + rank (no cursor atomics).
// Finalize: exact 2^-40 fixed-point integer atomic accumulation (associative
// => deterministic); last finisher writes out and restores counters to 0.

#define B_CONST 2
#define N_CONST 8192
#define KS_CONST 16
#define GRID 10
#define NCELLS 1000
#define TOTPTS 16384
#define R2LIM 0.0101f
#define D2SCALE 25900000.0f                        // 0.0101 * SCALE = 261590 < 2^18
#define RTHRESH_U 259000u                          // floor(0.01 * SCALE)
#define WPB 4                                      // warps (queries) per block
#define MAIN_TPB 128
#define MAIN_BLOCKS (TOTPTS / WPB)                // 4096
#define BUILD_TPB 1024
#define PPT 8                                      // consecutive points per build thread
#define FIXSCALE 1099511627776.0                   // 2^40

__device__ int                g_start [B_CONST * (NCELLS + 1)];
__device__ float4             g_sorted[TOTPTS];    // (x, y, z, idx-as-float-bits)
__device__ unsigned long long g_acc;               // fixed-point loss accumulator
__device__ int                g_done;

__device__ __forceinline__ int cell_of(float x, float y, float z) {
    int cx = min(max((int)(x * (float)GRID), 0), GRID - 1);
    int cy = min(max((int)(y * (float)GRID), 0), GRID - 1);
    int cz = min(max((int)(z * (float)GRID), 0), GRID - 1);
    return cx + GRID * (cy + GRID * cz);          // x fastest
}

// ---------------- grid build: one block per batch, single atomic pass ----------------

__global__ __launch_bounds__(BUILD_TPB) void k_build(const float* __restrict__ pc) {
    __shared__ int scnt[BUILD_TPB];                // counts -> (after scan) unused
    __shared__ int swoff[32];
    __shared__ int sstart[NCELLS];                 // exclusive prefix per cell

    const int b    = blockIdx.x;
    const int tid  = threadIdx.x;
    const int lane = tid & 31;
    const int wid  = tid >> 5;
    const float* pcb = pc + (size_t)b * N_CONST * 3;

    scnt[tid] = 0;
    __syncthreads();

    // one pass: 8 consecutive points = 6 float4 loads; keep all in registers
    const float4* pv = reinterpret_cast<const float4*>(pcb) + (size_t)tid * (3 * PPT / 4);
    float4 v0 = __ldg(pv + 0), v1 = __ldg(pv + 1), v2 = __ldg(pv + 2);
    float4 v3 = __ldg(pv + 3), v4 = __ldg(pv + 4), v5 = __ldg(pv + 5);

    float px[PPT], py[PPT], pz[PPT];
    px[0] = v0.x; py[0] = v0.y; pz[0] = v0.z;
    px[1] = v0.w; py[1] = v1.x; pz[1] = v1.y;
    px[2] = v1.z; py[2] = v1.w; pz[2] = v2.x;
    px[3] = v2.y; py[3] = v2.z; pz[3] = v2.w;
    px[4] = v3.x; py[4] = v3.y; pz[4] = v3.z;
    px[5] = v3.w; py[5] = v4.x; pz[5] = v4.y;
    px[6] = v4.z; py[6] = v4.w; pz[6] = v5.x;
    px[7] = v5.y; py[7] = v5.z; pz[7] = v5.w;

    int pcell[PPT], prank[PPT];
#pragma unroll
    for (int k = 0; k < PPT; ++k)
        pcell[k] = cell_of(px[k], py[k], pz[k]);
    // histogram atomic returns within-cell rank — the only atomic pass
#pragma unroll
    for (int k = 0; k < PPT; ++k)
        prank[k] = atomicAdd(&scnt[pcell[k]], 1);
    __syncthreads();

    int c = scnt[tid];
    int v = c;
#pragma unroll
    for (int o = 1; o < 32; o <<= 1) {
        int n = __shfl_up_sync(0xFFFFFFFFu, v, o);
        if (lane >= o) v += n;
    }
    if (lane == 31) swoff[wid] = v;
    __syncthreads();
    if (wid == 0) {
        int w = swoff[lane];
#pragma unroll
        for (int o = 1; o < 32; o <<= 1) {
            int n = __shfl_up_sync(0xFFFFFFFFu, w, o);
            if (lane >= o) w += n;
        }
        swoff[lane] = w;
    }
    __syncthreads();
    int incl = v + (wid ? swoff[wid - 1] : 0);
    int excl = incl - c;
    if (tid < NCELLS) {
        g_start[b * (NCELLS + 1) + tid] = excl;
        sstart[tid] = excl;
    }
    if (tid == NCELLS - 1) g_start[b * (NCELLS + 1) + NCELLS] = incl;
    __syncthreads();

    // scatter without atomics: pos = start[cell] + rank
#pragma unroll
    for (int k = 0; k < PPT; ++k) {
        int i   = tid * PPT + k;
        int pos = sstart[pcell[k]] + prank[k];
        g_sorted[b * N_CONST + pos] = make_float4(px[k], py[k], pz[k], __int_as_float(i));
    }
}

// ---------------- main: warp-per-query knn + loss + fused finalize ----------------

__global__ __launch_bounds__(MAIN_TPB) void knn_loss_main(const float* __restrict__ mask,
                                                          float* __restrict__ out) {
    __shared__ float swacc[WPB];

    const int warp  = threadIdx.x >> 5;
    const int lane  = threadIdx.x & 31;
    const int qslot = blockIdx.x * WPB + warp;
    const int b     = qslot >> 13;
    const int s     = qslot & (N_CONST - 1);

    const float4 me = g_sorted[b * N_CONST + s];     // broadcast across warp
    const float qx = me.x, qy = me.y, qz = me.z;
    const int   qi = __float_as_int(me.w);

    const int cx = min(max((int)(qx * (float)GRID), 0), GRID - 1);
    const int cy = min(max((int)(qy * (float)GRID), 0), GRID - 1);
    const int cz = min(max((int)(qz * (float)GRID), 0), GRID - 1);
    const int x0 = max(cx - 1, 0), x1 = min(cx + 1, GRID - 1);
    const int w  = x1 - x0 + 1;

    const int*    startb  = g_start  + b * (NCELLS + 1);
    const float4* sortedb = g_sorted + b * N_CONST;

    // lanes 0..8: fetch row bounds in parallel (validity + slab prune folded in)
    int beg_l = 0, end_l = 0;
    if (lane < 9) {
        const int rz = lane / 3;
        const int ry = lane - rz * 3;
        const int iyy = cy + ry - 1, izz = cz + rz - 1;
        bool valid = ((unsigned)iyy < GRID) && ((unsigned)izz < GRID);
        float fy = (float)iyy * 0.1f, fz = (float)izz * 0.1f;
        float dyv = fmaxf(fmaxf(fy - qy, qy - (fy + 0.1f)), 0.0f);
        float dzv = fmaxf(fmaxf(fz - qz, qz - (fz + 0.1f)), 0.0f);
        if (valid && (dyv * dyv + dzv * dzv <= R2LIM)) {
            int c0 = x0 + GRID * (iyy + GRID * izz);
            beg_l = __ldg(startb + c0);
            end_l = __ldg(startb + c0 + w);
        }
    }

    // per-lane sorted-4 smallest keys
    unsigned s0 = 0xFFFFFFFFu, s1 = 0xFFFFFFFFu, s2 = 0xFFFFFFFFu, s3 = 0xFFFFFFFFu;

    // row-granular software pipeline: row r+1's first-chunk LDG issues
    // before row r's compute/insert chain.
    int beg = __shfl_sync(0xFFFFFFFFu, beg_l, 0);
    int end = __shfl_sync(0xFFFFFFFFu, end_l, 0);
    float4 cur;
    bool curv = (beg + lane < end);
    if (curv) cur = __ldg(sortedb + beg + lane);

#pragma unroll
    for (int r = 0; r < 9; ++r) {
        int nbeg = 0, nend = 0;
        if (r < 8) {
            nbeg = __shfl_sync(0xFFFFFFFFu, beg_l, r + 1);
            nend = __shfl_sync(0xFFFFFFFFu, end_l, r + 1);
        }
        float4 nxt;
        bool nxtv = (r < 8) && (nbeg + lane < nend);
        if (nxtv) nxt = __ldg(sortedb + nbeg + lane);     // prefetch next row

        // process current row's first chunk
        {
            unsigned kk = 0xFFFFFFFFu;
            if (curv) {
                float dx = qx - cur.x, dy = qy - cur.y, dz = qz - cur.z;
                float d2 = fmaf(dx, dx, fmaf(dy, dy, dz * dz));
                if (d2 <= R2LIM)
                    kk = ((unsigned)(d2 * D2SCALE) << 13)
                       | (unsigned)__float_as_int(cur.w);
            }
            unsigned t0 = min(s0, kk), u0 = max(s0, kk);
            unsigned t1 = min(s1, u0), u1 = max(s1, u0);
            unsigned t2 = min(s2, u1), u2 = max(s2, u1);
            s3 = min(s3, u2);
            s0 = t0; s1 = t1; s2 = t2;
        }
        // rare overflow chunks (row > 32 candidates), uniform tail loop
        for (int p0 = beg + 32; p0 < end; p0 += 32) {
            const int p = p0 + lane;
            unsigned kk = 0xFFFFFFFFu;
            if (p < end) {
                float4 a = __ldg(sortedb + p);
                float dx = qx - a.x, dy = qy - a.y, dz = qz - a.z;
                float d2 = fmaf(dx, dx, fmaf(dy, dy, dz * dz));
                if (d2 <= R2LIM)
                    kk = ((unsigned)(d2 * D2SCALE) << 13)
                       | (unsigned)__float_as_int(a.w);
            }
            unsigned t0 = min(s0, kk), u0 = max(s0, kk);
            unsigned t1 = min(s1, u0), u1 = max(s1, u0);
            unsigned t2 = min(s2, u1), u2 = max(s2, u1);
            s3 = min(s3, u2);
            s0 = t0; s1 = t1; s2 = t2;
        }

        beg = nbeg; end = nend; cur = nxt; curv = nxtv;
    }

    // prefetch own mask row — overlaps the REDUX chain below
    const float* maskb = mask + (size_t)b * N_CONST * KS_CONST;
    const float4* mrow = reinterpret_cast<const float4*>(maskb + (size_t)qi * KS_CONST);
    float4 m0, m1, m2, m3;
    if (lane < 8) {
        m0 = __ldg(mrow);     m1 = __ldg(mrow + 1);
        m2 = __ldg(mrow + 2); m3 = __ldg(mrow + 3);
    }

    // ---- extract global top-8 via REDUX.MIN; winner r lands on lane r ----
    unsigned mykey = 0xFFFFFFFFu;
#pragma unroll
    for (int r = 0; r < 8; ++r) {
        unsigned wv = __reduce_min_sync(0xFFFFFFFFu, s0);
        if (lane == r) mykey = wv;
        bool own = (s0 == wv) && (wv != 0xFFFFFFFFu);
        s0 = own ? s1 : s0;
        s1 = own ? s2 : s1;
        s2 = own ? s3 : s2;
        s3 = own ? 0xFFFFFFFFu : s3;
    }

    // ---- loss terms: lanes 0-7 gather their neighbor's mask row ----
    float term = 0.0f;
    if (lane < 8 && mykey != 0xFFFFFFFFu) {
        unsigned uq = mykey >> 13;
        int      nb = (int)(mykey & 8191u);
        if (uq <= RTHRESH_U && nb != qi) {       // in radius, not self
            const float4* nrow = reinterpret_cast<const float4*>(maskb + (size_t)nb * KS_CONST);
            float4 n0 = __ldg(nrow), n1 = __ldg(nrow + 1), n2 = __ldg(nrow + 2), n3 = __ldg(nrow + 3);
            term  = fabsf(m0.x - n0.x) + fabsf(m0.y - n0.y) + fabsf(m0.z - n0.z) + fabsf(m0.w - n0.w);
            term += fabsf(m1.x - n1.x) + fabsf(m1.y - n1.y) + fabsf(m1.z - n1.z) + fabsf(m1.w - n1.w);
            term += fabsf(m2.x - n2.x) + fabsf(m2.y - n2.y) + fabsf(m2.z - n2.z) + fabsf(m2.w - n2.w);
            term += fabsf(m3.x - n3.x) + fabsf(m3.y - n3.y) + fabsf(m3.z - n3.z) + fabsf(m3.w - n3.w);
        }
    }
    // fixed shfl tree (deterministic association, lanes >= 8 contribute 0)
    term += __shfl_down_sync(0xFFFFFFFFu, term, 16);
    term += __shfl_down_sync(0xFFFFFFFFu, term, 8);
    term += __shfl_down_sync(0xFFFFFFFFu, term, 4);
    term += __shfl_down_sync(0xFFFFFFFFu, term, 2);
    term += __shfl_down_sync(0xFFFFFFFFu, term, 1);
    if (lane == 0) swacc[warp] = term;

    // ---- exact fixed-point integer accumulation (associative => deterministic) ----
    __syncthreads();
    if (threadIdx.x == 0) {
        float acc = (swacc[0] + swacc[1]) + (swacc[2] + swacc[3]);
        long long q = llrint((double)acc * FIXSCALE);     // exact for block partials
        atomicAdd(&g_acc, (unsigned long long)q);
        __threadfence();
        int old = atomicAdd(&g_done, 1);
        if (old == MAIN_BLOCKS - 1) {
            unsigned long long tot = atomicAdd(&g_acc, 0ull);
            out[0] = (float)((double)(long long)tot / FIXSCALE / (double)(TOTPTS * 8));
            g_acc  = 0ull;                                // restore for next replay
            g_done = 0;
        }
    }
}

extern "C" void kernel_launch(void* const* d_in, const int* in_sizes, int n_in,
                              void* d_out, int out_size) {
    const float* pc   = (const float*)d_in[0];   // (2, 8192, 3)  f32
    const float* mask = (const float*)d_in[1];   // (2, 8192, 16) f32
    float* out = (float*)d_out;                  // scalar f32

    k_build<<<B_CONST, BUILD_TPB>>>(pc);
    knn_loss_main<<<MAIN_BLOCKS, MAIN_TPB>>>(mask, out);
}